// round 6
// baseline (speedup 1.0000x reference)
#include <cuda_runtime.h>

// Shapes (fixed by the problem)
#define BB   4
#define LL   2048
#define DD   1024
#define VV   32
#define KK   4096
#define NTOK (BB*LL)     // 8192 tokens
#define TPB  32          // tokens per block (16 warps x 2)
#define TILE 128         // codes per smem tile
#define NTILE (KK/TILE)  // 32 tiles

// Scratch (static device globals — no allocation)
__device__ float g_embn[KK*VV];    // normalized codebook
__device__ float g_ne2[KK];        // sum(emb_n^2) + 1 per code (softmax shift folded)
__device__ float g_wpiT[VV*DD];    // Wpi transposed: [v][d]
__device__ float g_wpT4[DD*VV];    // Wp interleaved: [(d/4)][v][d%4] -> coalesced float4 loads

typedef unsigned long long ull;

__device__ __forceinline__ ull fma2(ull a, ull b, ull c){
    ull d;
    asm("fma.rn.f32x2 %0, %1, %2, %3;" : "=l"(d) : "l"(a), "l"(b), "l"(c));
    return d;
}
__device__ __forceinline__ ull pack2(float x, float y){
    ull r;
    asm("mov.b64 %0, {%1, %2};" : "=l"(r) : "f"(x), "f"(y));
    return r;
}
__device__ __forceinline__ float2 unpack2(ull a){
    float x, y;
    asm("mov.b64 {%0, %1}, %2;" : "=f"(x), "=f"(y) : "l"(a));
    return make_float2(x, y);
}
// volatile LDS.128 broadcast — prevents ptxas from hoisting into registers
__device__ __forceinline__ ulonglong2 lds128v(const ull* p){
    ulonglong2 r;
    unsigned a = (unsigned)__cvta_generic_to_shared((const void*)p);
    asm volatile("ld.shared.v2.u64 {%0, %1}, [%2];" : "=l"(r.x), "=l"(r.y) : "r"(a));
    return r;
}
__device__ __forceinline__ void cp16(void* dst, const void* src){
    unsigned s = (unsigned)__cvta_generic_to_shared(dst);
    asm volatile("cp.async.cg.shared.global [%0], [%1], 16;" :: "r"(s), "l"(src));
}
__device__ __forceinline__ void cp4(void* dst, const void* src){
    unsigned s = (unsigned)__cvta_generic_to_shared(dst);
    asm volatile("cp.async.ca.shared.global [%0], [%1], 4;" :: "r"(s), "l"(src));
}

// ---------------------------------------------------------------------------
// Merged prep kernel:
//   blocks [0,512)   : normalize codebook rows, g_ne2 = sum(emb_n^2) + 1
//   blocks [512,640) : transpose Wpi [D,V] -> WpiT [V,D]; write vq_loss = 0
//   blocks [640,768) : build interleaved WpT4
// ---------------------------------------------------------------------------
__global__ void prep_kernel(const float* __restrict__ emb,
                            const float* __restrict__ Wpi,
                            const float* __restrict__ Wp,
                            float* __restrict__ out, long long out_size){
    int b = blockIdx.x;
    if(b < 512){
        int r = b * 8 + (threadIdx.x >> 5);
        int v = threadIdx.x & 31;
        float val = emb[r*VV + v];
        float ss = val * val;
        #pragma unroll
        for(int o=16;o;o>>=1) ss += __shfl_xor_sync(0xffffffffu, ss, o);
        float en = val * rsqrtf(ss);
        g_embn[r*VV + v] = en;
        float s2 = en * en;
        #pragma unroll
        for(int o=16;o;o>>=1) s2 += __shfl_xor_sync(0xffffffffu, s2, o);
        if(v == 0) g_ne2[r] = s2 + 1.0f;   // +1: fixed softmax shift folded in
    } else if(b < 640){
        int i = (b - 512) * 256 + threadIdx.x;   // over D*V
        int d = i >> 5, v = i & 31;              // Wpi[d][v]
        g_wpiT[v*DD + d] = Wpi[i];
        if(i == 0){
            long long qn = (long long)NTOK * DD;
            if(out_size >= qn + NTOK + 1) out[qn + NTOK] = 0.0f;  // vq_loss
        }
    } else {
        int i = (b - 640) * 256 + threadIdx.x;   // over V*D (coalesced Wp read)
        int v = i >> 10, d = i & 1023;           // Wp[v][d]
        g_wpT4[(d >> 2)*128 + v*4 + (d & 3)] = Wp[i];
    }
}

// ---------------------------------------------------------------------------
// Main fused kernel: 512 threads, 16 warps, 2 tokens/warp, hp via smem bcast
// ---------------------------------------------------------------------------
__global__ void __launch_bounds__(512, 1)
vq_main_kernel(const float* __restrict__ h,
               const float* __restrict__ attn_mask,
               const float* __restrict__ bp,
               const float* __restrict__ bpi,
               float* __restrict__ out, long long out_size)
{
    // row pad 36 floats (144B): LDS.128 conflict-free (8-lane phases)
    __shared__ __align__(16) float s_e[2][TILE*36];   // 36.9 KB, reused as reduce scratch
    __shared__ __align__(16) float s_ne2[2][TILE];    // 1 KB
    __shared__ __align__(16) ull   s_hp2[16*32];      // 4 KB: per warp 16 entries of {A-pair, B-pair}
    __shared__ __align__(16) float s_q[TPB*32];       // 4 KB masked soft-quantized vectors

    const int tid  = threadIdx.x;
    const int w    = tid >> 5;        // 0..15
    const int lane = tid & 31;
    const int tokA = blockIdx.x * TPB + 2*w;
    const int tokB = tokA + 1;

    // ---- kick off tile 0 load (overlaps with phase 1) ----
    {
        const float* src = g_embn;  // tile 0
        #pragma unroll
        for(int r=0;r<2;r++){
            int idx = tid + 512*r;            // 0..1023
            int c = idx >> 3, u = idx & 7;
            cp16(&s_e[0][c*36 + u*4], src + c*VV + u*4);
        }
        if(tid < TILE) cp4(&s_ne2[0][tid], g_ne2 + tid);
        asm volatile("cp.async.commit_group;");
    }

    // ---- phase 1: hp = h @ Wp^T + bp via interleaved WpT4 (coalesced) ----
    {
        const float4* hA4 = (const float4*)(h + (long long)tokA * DD);
        const float4* hB4 = (const float4*)(h + (long long)tokB * DD);
        const float4* wT  = (const float4*)g_wpT4;
        float bpl = __ldg(bp + lane);
        float dA = bpl, dB = bpl;
        #pragma unroll 8
        for(int g=0;g<DD/4;g++){
            float4 wv = __ldg(wT + g*32 + lane);   // lane-consecutive
            float4 a  = __ldg(hA4 + g);            // warp-uniform broadcast
            float4 b  = __ldg(hB4 + g);
            dA += wv.x*a.x + wv.y*a.y + wv.z*a.z + wv.w*a.w;
            dB += wv.x*b.x + wv.y*b.y + wv.z*b.z + wv.w*b.w;
        }
        float ssA = dA*dA, ssB = dB*dB;
        #pragma unroll
        for(int o=16;o;o>>=1){
            ssA += __shfl_xor_sync(0xffffffffu, ssA, o);
            ssB += __shfl_xor_sync(0xffffffffu, ssB, o);
        }
        // interleaved layout: warp region = 64 floats, entry u = {A[2u],A[2u+1],B[2u],B[2u+1]}
        float* hp2f = ((float*)s_hp2) + w*64;
        int ia = ((lane >> 1) << 2) | (lane & 1);
        hp2f[ia]     = dA * (2.0f * rsqrtf(ssA));   // store 2*normalized hp
        hp2f[ia + 2] = dB * (2.0f * rsqrtf(ssB));
        __syncwarp();
    }

    // ---- main loop: online softmax over K with fixed shift (folded into ne2) ----
    ull accA[16], accB[16];
    #pragma unroll
    for(int u=0;u<16;u++){ accA[u]=0ull; accB[u]=0ull; }
    float lA = 0.f, lB = 0.f;
    float bestA = -1e30f, bestB = -1e30f;
    int   idxA = 0, idxB = 0;

    const ull* hp2base = s_hp2 + w*32;

    for(int t=0;t<NTILE;t++){
        const int buf = t & 1;
        if(t + 1 < NTILE){
            const float* src = g_embn + (t+1)*TILE*VV;
            #pragma unroll
            for(int r=0;r<2;r++){
                int idx = tid + 512*r;
                int c = idx >> 3, u = idx & 7;
                cp16(&s_e[buf^1][c*36 + u*4], src + c*VV + u*4);
            }
            if(tid < TILE) cp4(&s_ne2[buf^1][tid], g_ne2 + (t+1)*TILE + tid);
        }
        asm volatile("cp.async.commit_group;");
        asm volatile("cp.async.wait_group 1;");
        __syncthreads();

        #pragma unroll 1
        for(int j=0;j<4;j++){
            const int c = lane + 32*j;
            const ulonglong2* er = (const ulonglong2*)&s_e[buf][c*36];
            ull e[16];
            #pragma unroll
            for(int u=0;u<8;u++){ ulonglong2 x = er[u]; e[2*u] = x.x; e[2*u+1] = x.y; }

            ull sA = 0ull, sB = 0ull;
            #pragma unroll
            for(int u=0;u<16;u++){
                ulonglong2 hp2 = lds128v(hp2base + 2*u);   // broadcast, not hoistable
                sA = fma2(hp2.x, e[u], sA);
                sB = fma2(hp2.y, e[u], sB);
            }
            float2 fa = unpack2(sA), fb = unpack2(sB);
            float ne2p1 = s_ne2[buf][c];
            float scA = (fa.x + fa.y) - ne2p1;     // = 2*s - ne2 - 1 (shifted score)
            float scB = (fb.x + fb.y) - ne2p1;
            int   code = t*TILE + c;
            if(scA > bestA){ bestA = scA; idxA = code; }
            if(scB > bestB){ bestB = scB; idxB = code; }
            float pA = __expf(scA);
            float pB = __expf(scB);
            lA += pA; lB += pB;
            ull ppA = pack2(pA, pA), ppB = pack2(pB, pB);
            #pragma unroll
            for(int u=0;u<16;u++){
                accA[u] = fma2(ppA, e[u], accA[u]);
                accB[u] = fma2(ppB, e[u], accB[u]);
            }
        }
        __syncthreads();   // before overwriting this buffer next iteration
    }

    // ---- cross-lane reduction: two warp-group phases (scratch = 8 warps' worth) ----
    const long long qn = (long long)NTOK * DD;
    float mkA = (attn_mask[tokA] == 1.0f) ? 1.0f : 0.0f;
    float mkB = (attn_mask[tokB] == 1.0f) ? 1.0f : 0.0f;

    #pragma unroll 1
    for(int ph=0; ph<2; ph++){
        if((w >> 3) == ph){
            float* red  = ((float*)s_e) + (w & 7) * 1088;   // 32 lanes * 34 floats (pad 2)
            ull*   redu = (ull*)red;
            // token A
            {
                #pragma unroll
                for(int jj=0;jj<16;jj++) redu[lane*17 + jj] = accA[jj];
                __syncwarp();
                float q = 0.f;
                #pragma unroll
                for(int l2=0;l2<32;l2++) q += red[l2*34 + lane];
                float lt = lA;
                #pragma unroll
                for(int o=16;o;o>>=1) lt += __shfl_xor_sync(0xffffffffu, lt, o);
                float bv = bestA; int bi = idxA;
                #pragma unroll
                for(int o=16;o;o>>=1){
                    float ov = __shfl_down_sync(0xffffffffu, bv, o);
                    int   oi = __shfl_down_sync(0xffffffffu, bi, o);
                    if(ov > bv || (ov == bv && oi < bi)){ bv = ov; bi = oi; }
                }
                s_q[(2*w)*32 + lane] = q * (mkA / lt);
                if(lane == 0 && out_size >= qn + NTOK) out[qn + tokA] = mkA * (float)bi;
                __syncwarp();
            }
            // token B
            {
                #pragma unroll
                for(int jj=0;jj<16;jj++) redu[lane*17 + jj] = accB[jj];
                __syncwarp();
                float q = 0.f;
                #pragma unroll
                for(int l2=0;l2<32;l2++) q += red[l2*34 + lane];
                float lt = lB;
                #pragma unroll
                for(int o=16;o;o>>=1) lt += __shfl_xor_sync(0xffffffffu, lt, o);
                float bv = bestB; int bi = idxB;
                #pragma unroll
                for(int o=16;o;o>>=1){
                    float ov = __shfl_down_sync(0xffffffffu, bv, o);
                    int   oi = __shfl_down_sync(0xffffffffu, bi, o);
                    if(ov > bv || (ov == bv && oi < bi)){ bv = ov; bi = oi; }
                }
                s_q[(2*w+1)*32 + lane] = q * (mkB / lt);
                if(lane == 0 && out_size >= qn + NTOK) out[qn + tokB] = mkB * (float)bi;
                __syncwarp();
            }
        }
        __syncthreads();
    }

    // ---- epilogue: out = q @ Wpi^T + bpi (both tokens share WpiT loads) ----
    {
        float4 oA[8], oB[8];
        #pragma unroll
        for(int m=0;m<8;m++){ oA[m] = make_float4(0,0,0,0); oB[m] = make_float4(0,0,0,0); }
        #pragma unroll 2
        for(int v=0;v<32;v++){
            float qa = s_q[(2*w)*32 + v];      // smem broadcast
            float qb = s_q[(2*w+1)*32 + v];
            const float4* wr = (const float4*)(g_wpiT + v*DD);
            #pragma unroll
            for(int m=0;m<8;m++){
                float4 wv = __ldg(wr + m*32 + lane);   // d = 128*m + 4*lane, coalesced
                oA[m].x += qa*wv.x; oA[m].y += qa*wv.y; oA[m].z += qa*wv.z; oA[m].w += qa*wv.w;
                oB[m].x += qb*wv.x; oB[m].y += qb*wv.y; oB[m].z += qb*wv.z; oB[m].w += qb*wv.w;
            }
        }
        float4* outA = (float4*)(out + (long long)tokA * DD);
        float4* outB = (float4*)(out + (long long)tokB * DD);
        const float4* bp4 = (const float4*)bpi;
        #pragma unroll
        for(int m=0;m<8;m++){
            float4 bv = __ldg(bp4 + m*32 + lane);
            float4 a = oA[m]; a.x += bv.x; a.y += bv.y; a.z += bv.z; a.w += bv.w;
            float4 b = oB[m]; b.x += bv.x; b.y += bv.y; b.z += bv.z; b.w += bv.w;
            outA[m*32 + lane] = a;
            outB[m*32 + lane] = b;
        }
    }
}

extern "C" void kernel_launch(void* const* d_in, const int* in_sizes, int n_in,
                              void* d_out, int out_size)
{
    const float* h    = (const float*)d_in[0];   // [B,L,D]
    const float* mask = (const float*)d_in[1];   // [B,L]
    const float* Wp   = (const float*)d_in[2];   // [V,D]
    const float* bp   = (const float*)d_in[3];   // [V]
    const float* Wpi  = (const float*)d_in[4];   // [D,V]
    const float* bpi  = (const float*)d_in[5];   // [D]
    const float* emb  = (const float*)d_in[6];   // [K,V]
    float* out = (float*)d_out;
    long long osz = (long long)out_size;

    prep_kernel<<<768, 256>>>(emb, Wpi, Wp, out, osz);
    vq_main_kernel<<<NTOK/TPB, 512>>>(h, mask, bp, bpi, out, osz);
}

// round 7
// speedup vs baseline: 1.5601x; 1.5601x over previous
#include <cuda_runtime.h>

// Shapes (fixed by the problem)
#define BB   4
#define LL   2048
#define DD   1024
#define VV   32
#define KK   4096
#define NTOK (BB*LL)     // 8192 tokens
#define TPB  32          // tokens per block (= warp lanes; lane t owns token t)
#define NW   8           // warps per block (each owns a K-slice)
#define KW   (KK/NW)     // 512 codes per warp
#define CT   32          // codes per smem tile
#define NT2  (KW/CT)     // 16 tiles per warp

// Scratch (static device globals — no allocation)
__device__ float g_embn[KK*VV];    // normalized codebook
__device__ float g_ne2[KK];        // sum(emb_n^2) + 1 per code (softmax shift folded)
__device__ float g_wpiT[VV*DD];    // Wpi transposed: [v][d]
__device__ float g_wpT4[DD*VV];    // Wp interleaved: [(d/4)][v][d%4] -> coalesced float4

typedef unsigned long long ull;

__device__ __forceinline__ ull fma2(ull a, ull b, ull c){
    ull d;
    asm("fma.rn.f32x2 %0, %1, %2, %3;" : "=l"(d) : "l"(a), "l"(b), "l"(c));
    return d;
}
__device__ __forceinline__ ull pack2(float x, float y){
    ull r;
    asm("mov.b64 %0, {%1, %2};" : "=l"(r) : "f"(x), "f"(y));
    return r;
}
__device__ __forceinline__ float2 unpack2(ull a){
    float x, y;
    asm("mov.b64 {%0, %1}, %2;" : "=f"(x), "=f"(y) : "l"(a));
    return make_float2(x, y);
}
__device__ __forceinline__ void cp16(void* dst, const void* src){
    unsigned s = (unsigned)__cvta_generic_to_shared(dst);
    asm volatile("cp.async.cg.shared.global [%0], [%1], 16;" :: "r"(s), "l"(src));
}
__device__ __forceinline__ void cp4(void* dst, const void* src){
    unsigned s = (unsigned)__cvta_generic_to_shared(dst);
    asm volatile("cp.async.ca.shared.global [%0], [%1], 4;" :: "r"(s), "l"(src));
}

// ---------------------------------------------------------------------------
// Merged prep kernel (unchanged from R5)
// ---------------------------------------------------------------------------
__global__ void prep_kernel(const float* __restrict__ emb,
                            const float* __restrict__ Wpi,
                            const float* __restrict__ Wp,
                            float* __restrict__ out, long long out_size){
    int b = blockIdx.x;
    if(b < 512){
        int r = b * 8 + (threadIdx.x >> 5);
        int v = threadIdx.x & 31;
        float val = emb[r*VV + v];
        float ss = val * val;
        #pragma unroll
        for(int o=16;o;o>>=1) ss += __shfl_xor_sync(0xffffffffu, ss, o);
        float en = val * rsqrtf(ss);
        g_embn[r*VV + v] = en;
        float s2 = en * en;
        #pragma unroll
        for(int o=16;o;o>>=1) s2 += __shfl_xor_sync(0xffffffffu, s2, o);
        if(v == 0) g_ne2[r] = s2 + 1.0f;   // +1: fixed softmax shift folded in
    } else if(b < 640){
        int i = (b - 512) * 256 + threadIdx.x;   // over D*V
        int d = i >> 5, v = i & 31;              // Wpi[d][v]
        g_wpiT[v*DD + d] = Wpi[i];
        if(i == 0){
            long long qn = (long long)NTOK * DD;
            if(out_size >= qn + NTOK + 1) out[qn + NTOK] = 0.0f;  // vq_loss
        }
    } else {
        int i = (b - 640) * 256 + threadIdx.x;   // over V*D (coalesced Wp read)
        int v = i >> 10, d = i & 1023;           // Wp[v][d]
        g_wpT4[(d >> 2)*128 + v*4 + (d & 3)] = Wp[i];
    }
}

// ---------------------------------------------------------------------------
// Main fused kernel: token-major lanes, K-sliced warps, occ-2
// ---------------------------------------------------------------------------
__global__ void __launch_bounds__(256, 2)
vq_main_kernel(const float* __restrict__ h,
               const float* __restrict__ attn_mask,
               const float* __restrict__ bp,
               const float* __restrict__ bpi,
               float* __restrict__ out, long long out_size)
{
    __shared__ __align__(16) float s_e[NW][2][CT*VV];   // 64 KB (also reused for partials)
    __shared__ __align__(16) float s_ne2[NW][2][CT];    // 2 KB
    __shared__ __align__(16) float s_hp[TPB*36];        // 4.6 KB (padded rows)
    __shared__ __align__(16) float4 s_comb[NW*TPB];     // 4 KB {l, best, idx, -}
    __shared__ __align__(16) float s_scale[TPB];
    __shared__ __align__(16) float s_q[TPB*VV];         // 4 KB

    const int tid  = threadIdx.x;
    const int w    = tid >> 5;        // 0..7 : K-slice id
    const int lane = tid & 31;        // token id within block
    const int blk  = blockIdx.x;
    const long long qn = (long long)NTOK * DD;

    // ---- prefetch this warp's tile 0 (overlaps phase 1) ----
    {
        const float* src = g_embn + (w*KW)*VV;
        #pragma unroll
        for(int r=0;r<8;r++){
            int i = lane + 32*r;      // 256 x 16B chunks = 4KB
            cp16(&s_e[w][0][i*4], src + i*4);
        }
        cp4(&s_ne2[w][0][lane], g_ne2 + w*KW + lane);
        asm volatile("cp.async.commit_group;");
    }

    // ---- phase 1: hp for 4 tokens per warp (lane = v index) ----
    {
        const int tok0 = blk*TPB + 4*w;
        const float4* h0 = (const float4*)(h + (long long)(tok0  )*DD);
        const float4* h1 = (const float4*)(h + (long long)(tok0+1)*DD);
        const float4* h2 = (const float4*)(h + (long long)(tok0+2)*DD);
        const float4* h3 = (const float4*)(h + (long long)(tok0+3)*DD);
        const float4* wT = (const float4*)g_wpT4;
        float bpl = __ldg(bp + lane);
        float d0=bpl, d1=bpl, d2=bpl, d3=bpl;
        #pragma unroll 4
        for(int g=0;g<DD/4;g++){
            float4 wv = __ldg(wT + g*32 + lane);   // lane-consecutive
            float4 a  = __ldg(h0 + g);
            d0 += wv.x*a.x + wv.y*a.y + wv.z*a.z + wv.w*a.w;
            float4 b  = __ldg(h1 + g);
            d1 += wv.x*b.x + wv.y*b.y + wv.z*b.z + wv.w*b.w;
            float4 c  = __ldg(h2 + g);
            d2 += wv.x*c.x + wv.y*c.y + wv.z*c.z + wv.w*c.w;
            float4 e  = __ldg(h3 + g);
            d3 += wv.x*e.x + wv.y*e.y + wv.z*e.z + wv.w*e.w;
        }
        float s0=d0*d0, s1=d1*d1, s2=d2*d2, s3=d3*d3;
        #pragma unroll
        for(int o=16;o;o>>=1){
            s0 += __shfl_xor_sync(0xffffffffu, s0, o);
            s1 += __shfl_xor_sync(0xffffffffu, s1, o);
            s2 += __shfl_xor_sync(0xffffffffu, s2, o);
            s3 += __shfl_xor_sync(0xffffffffu, s3, o);
        }
        s_hp[(4*w  )*36 + lane] = d0 * (2.0f * rsqrtf(s0));  // 2*normalized hp
        s_hp[(4*w+1)*36 + lane] = d1 * (2.0f * rsqrtf(s1));
        s_hp[(4*w+2)*36 + lane] = d2 * (2.0f * rsqrtf(s2));
        s_hp[(4*w+3)*36 + lane] = d3 * (2.0f * rsqrtf(s3));
    }
    __syncthreads();

    // ---- each lane loads ITS token's hp into registers ----
    ull hp[16];
    {
        const ulonglong2* hr = (const ulonglong2*)&s_hp[lane*36];  // 144B rows, 16B aligned
        #pragma unroll
        for(int u=0;u<8;u++){ ulonglong2 x = hr[u]; hp[2*u] = x.x; hp[2*u+1] = x.y; }
    }

    // ---- main loop over this warp's K-slice (warp-private pipeline) ----
    ull acc[16];
    #pragma unroll
    for(int u=0;u<16;u++) acc[u] = 0ull;
    float l = 0.f, best = -1e30f;
    int   idx = 0;
    const int cbase = w*KW;

    for(int t2=0;t2<NT2;t2++){
        const int buf = t2 & 1;
        if(t2 + 1 < NT2){
            const float* src = g_embn + (cbase + (t2+1)*CT)*VV;
            #pragma unroll
            for(int r=0;r<8;r++){
                int i = lane + 32*r;
                cp16(&s_e[w][buf^1][i*4], src + i*4);
            }
            cp4(&s_ne2[w][buf^1][lane], g_ne2 + cbase + (t2+1)*CT + lane);
            asm volatile("cp.async.commit_group;");
            asm volatile("cp.async.wait_group 1;");
        } else {
            asm volatile("cp.async.wait_group 0;");
        }
        __syncwarp();

        #pragma unroll 1
        for(int j=0;j<CT;j++){
            const ulonglong2* er = (const ulonglong2*)&s_e[w][buf][j*VV];  // broadcast
            ull e[16];
            #pragma unroll
            for(int u=0;u<8;u++){ ulonglong2 x = er[u]; e[2*u] = x.x; e[2*u+1] = x.y; }

            // 4 parallel partial score chains (depth 4 instead of 16)
            ull p0=0ull, p1=0ull, p2=0ull, p3=0ull;
            #pragma unroll
            for(int u=0;u<4;u++){
                p0 = fma2(hp[u   ], e[u   ], p0);
                p1 = fma2(hp[4+u ], e[4+u ], p1);
                p2 = fma2(hp[8+u ], e[8+u ], p2);
                p3 = fma2(hp[12+u], e[12+u], p3);
            }
            float2 f0 = unpack2(p0), f1 = unpack2(p1), f2 = unpack2(p2), f3 = unpack2(p3);
            float sc = ((f0.x+f0.y) + (f1.x+f1.y)) + ((f2.x+f2.y) + (f3.x+f3.y))
                     - s_ne2[w][buf][j];              // = 2*s - ne2 - 1 (shifted)
            int code = cbase + t2*CT + j;
            if(sc > best){ best = sc; idx = code; }
            float p = __expf(sc);                     // shifted score <= ~3e-4
            l += p;
            ull pp = pack2(p, p);
            #pragma unroll
            for(int u=0;u<16;u++) acc[u] = fma2(pp, e[u], acc[u]);
        }
    }

    // ---- write per-warp partials (overlay s_e; all warps done reading) ----
    __syncthreads();
    {
        float* prow = ((float*)s_e) + (w*TPB + lane)*36;   // padded rows
        ulonglong2* pr2 = (ulonglong2*)prow;
        #pragma unroll
        for(int u=0;u<8;u++){ ulonglong2 x; x.x = acc[2*u]; x.y = acc[2*u+1]; pr2[u] = x; }
        s_comb[w*TPB + lane] = make_float4(l, best, __int_as_float(idx), 0.f);
    }
    __syncthreads();

    // ---- cross-warp combine: 8 threads per token ----
    {
        const int t = tid >> 3, g = tid & 7;
        float4 sum = make_float4(0.f,0.f,0.f,0.f);
        #pragma unroll
        for(int ww=0;ww<NW;ww++){
            const float4* pr = (const float4*)(((float*)s_e) + (ww*TPB + t)*36);
            float4 v = pr[g];
            sum.x += v.x; sum.y += v.y; sum.z += v.z; sum.w += v.w;
        }
        if(g == 0){
            float lt = 0.f, bv = -1e30f; int bi = 0;
            #pragma unroll
            for(int ww=0;ww<NW;ww++){
                float4 c = s_comb[ww*TPB + t];
                lt += c.x;
                if(c.y > bv){ bv = c.y; bi = __float_as_int(c.z); }   // ascending slices: first max kept
            }
            float mk = (attn_mask[blk*TPB + t] == 1.0f) ? 1.0f : 0.0f;
            s_scale[t] = mk / lt;
            if(out_size >= qn + NTOK) out[qn + blk*TPB + t] = mk * (float)bi;
        }
        __syncthreads();
        float scl = s_scale[t];
        float4 qv = make_float4(sum.x*scl, sum.y*scl, sum.z*scl, sum.w*scl);
        ((float4*)(s_q + t*VV))[g] = qv;
    }
    __syncthreads();

    // ---- epilogue: out = q @ Wpi^T + bpi; warp w -> tokens 4w..4w+3, 2 passes ----
    #pragma unroll 1
    for(int ps=0; ps<2; ps++){
        const int tA = 4*w + 2*ps, tB = tA + 1;
        float4 oA[8], oB[8];
        #pragma unroll
        for(int m=0;m<8;m++){ oA[m] = make_float4(0,0,0,0); oB[m] = make_float4(0,0,0,0); }
        #pragma unroll 2
        for(int v=0;v<VV;v++){
            float qa = s_q[tA*VV + v];      // smem broadcast
            float qb = s_q[tB*VV + v];
            const float4* wr = (const float4*)(g_wpiT + v*DD);
            #pragma unroll
            for(int m=0;m<8;m++){
                float4 wv = __ldg(wr + m*32 + lane);   // d = 128*m + 4*lane, coalesced (L1-hot)
                oA[m].x += qa*wv.x; oA[m].y += qa*wv.y; oA[m].z += qa*wv.z; oA[m].w += qa*wv.w;
                oB[m].x += qb*wv.x; oB[m].y += qb*wv.y; oB[m].z += qb*wv.z; oB[m].w += qb*wv.w;
            }
        }
        float4* outA = (float4*)(out + (long long)(blk*TPB + tA) * DD);
        float4* outB = (float4*)(out + (long long)(blk*TPB + tB) * DD);
        const float4* bp4 = (const float4*)bpi;
        #pragma unroll
        for(int m=0;m<8;m++){
            float4 bv = __ldg(bp4 + m*32 + lane);
            float4 a = oA[m]; a.x += bv.x; a.y += bv.y; a.z += bv.z; a.w += bv.w;
            float4 b = oB[m]; b.x += bv.x; b.y += bv.y; b.z += bv.z; b.w += bv.w;
            outA[m*32 + lane] = a;
            outB[m*32 + lane] = b;
        }
    }
}

extern "C" void kernel_launch(void* const* d_in, const int* in_sizes, int n_in,
                              void* d_out, int out_size)
{
    const float* h    = (const float*)d_in[0];   // [B,L,D]
    const float* mask = (const float*)d_in[1];   // [B,L]
    const float* Wp   = (const float*)d_in[2];   // [V,D]
    const float* bp   = (const float*)d_in[3];   // [V]
    const float* Wpi  = (const float*)d_in[4];   // [D,V]
    const float* bpi  = (const float*)d_in[5];   // [D]
    const float* emb  = (const float*)d_in[6];   // [K,V]
    float* out = (float*)d_out;
    long long osz = (long long)out_size;

    prep_kernel<<<768, 256>>>(emb, Wpi, Wp, out, osz);
    vq_main_kernel<<<NTOK/TPB, 256>>>(h, mask, bp, bpi, out, osz);
}